// round 11
// baseline (speedup 1.0000x reference)
#include <cuda_runtime.h>
#include <cuda_fp16.h>
#include <math.h>

#define F0   128
#define HID  64
#define NG   64
#define NC   10
#define MAXN 100000
#define MAXE 1600000
#define SCAN_B 512
#define MAX_PART 256

// ---- scratch (no allocs allowed) ----
__device__ int    g_is64;
__device__ int    g_idc [MAXN];
__device__ float  g_dinv[MAXN];
__device__ int    g_rowstart[MAXN + 1];
__device__ int    g_cursor[MAXN];
__device__ int    g_part[MAX_PART];
__device__ int2   g_cedge[MAXE];         // CSR slot: (src, float_as_int(norm))
__device__ __half g_h   [MAXN * HID];    // h = act @ W   (fp16, pre-relu)
__device__ __half g_act [MAXN * HID];    // relu(agg)     (fp16)
__device__ float  g_pool[NG * HID];
__device__ float  g_cnt [NG];

__device__ __forceinline__ int fetch_idx(const void* p, long long i) {
    if (g_is64) return (int)((const long long*)p)[i];
    return ((const int*)p)[i];
}

// ---------------- fused init: dtype detect + zero idc + zero pool ----------
__global__ void k_init(const int* __restrict__ ei, int n) {
    int i = blockIdx.x * blockDim.x + threadIdx.x;
    if (i < n) g_idc[i] = 0;
    if (i < NG * HID) g_pool[i] = 0.0f;
    if (i < NG) g_cnt[i] = 0.0f;
    if (blockIdx.x == 0) {
        __shared__ int s[256];
        int acc = 0;
        for (int j = threadIdx.x; j < 1024; j += 256) acc |= ei[2 * j + 1];
        s[threadIdx.x] = acc;
        __syncthreads();
        for (int d = 128; d; d >>= 1) {
            if (threadIdx.x < d) s[threadIdx.x] |= s[threadIdx.x + d];
            __syncthreads();
        }
        if (threadIdx.x == 0) g_is64 = (s[0] == 0) ? 1 : 0;
    }
}

__global__ void k_deg(const void* __restrict__ ei, int e) {
    int i = blockIdx.x * blockDim.x + threadIdx.x;
    if (i < e) atomicAdd(&g_idc[fetch_idx(ei, (long long)e + i)], 1);
}

// ---------------- scan (+ dinv fused) ----------------
__global__ void k_scan1(int n) {
    __shared__ int s[SCAN_B];
    int i = blockIdx.x * SCAN_B + threadIdx.x;
    int v = (i < n) ? g_idc[i] : 0;
    if (i < n) g_dinv[i] = rsqrtf((float)(v + 1));
    s[threadIdx.x] = v;
    __syncthreads();
    int incl = v;
    #pragma unroll
    for (int d = 1; d < SCAN_B; d <<= 1) {
        int t = (threadIdx.x >= d) ? s[threadIdx.x - d] : 0;
        __syncthreads();
        incl += t;
        s[threadIdx.x] = incl;
        __syncthreads();
    }
    if (i < n) g_rowstart[i] = incl - v;
    if (threadIdx.x == SCAN_B - 1) g_part[blockIdx.x] = incl;
}
__global__ void k_scan2(int nb) {
    __shared__ int s[MAX_PART];
    int v = (threadIdx.x < nb) ? g_part[threadIdx.x] : 0;
    s[threadIdx.x] = v;
    __syncthreads();
    int incl = v;
    #pragma unroll
    for (int d = 1; d < MAX_PART; d <<= 1) {
        int t = (threadIdx.x >= d) ? s[threadIdx.x - d] : 0;
        __syncthreads();
        incl += t;
        s[threadIdx.x] = incl;
        __syncthreads();
    }
    if (threadIdx.x < nb) g_part[threadIdx.x] = incl - v;
}
__global__ void k_scan3(int n, int e) {
    int i = blockIdx.x * blockDim.x + threadIdx.x;
    if (i < n) {
        int r = g_rowstart[i] + g_part[i / SCAN_B];
        g_rowstart[i] = r;
        g_cursor[i] = r;
    }
    if (i == 0) g_rowstart[n] = e;
}

__global__ void k_fill(const void* __restrict__ ei, int e) {
    int i = blockIdx.x * blockDim.x + threadIdx.x;
    if (i < e) {
        int s = fetch_idx(ei, i);
        int d = fetch_idx(ei, (long long)e + i);
        int pos = atomicAdd(&g_cursor[d], 1);
        g_cedge[pos] = make_int2(s, __float_as_int(g_dinv[s] * g_dinv[d]));
    }
}

// ---------------- GEMM (tensor cores): g_h(fp16) = A @ W ---------------------
template<int F_IN, bool FP16IN>
__global__ void __launch_bounds__(256) k_gemm(const float* __restrict__ in32,
                                              const float* __restrict__ W, int n) {
    constexpr int ST = F_IN + 8;               // smem stride in halves
    __shared__ __half As [64 * ST];
    __shared__ __half WTs[64 * ST];            // W^T: [n][k]
    const int tid   = threadIdx.x;
    const int row0  = blockIdx.x * 64;
    const int lane  = tid & 31;
    const int warp  = tid >> 5;
    const int wr    = warp >> 1;               // row group 0..3
    const int wc    = warp & 1;                // col group 0..1
    const int l4    = lane >> 2;
    const int l2    = (lane & 3) * 2;

    if (FP16IN) {
        #pragma unroll
        for (int i = tid; i < 64 * (F_IN / 8); i += 256) {
            int r = i / (F_IN / 8), c8 = i % (F_IN / 8);
            int row = row0 + r;
            uint4 v = make_uint4(0u, 0u, 0u, 0u);
            if (row < n) v = *(const uint4*)&g_act[(size_t)row * HID + c8 * 8];
            *(uint4*)&As[r * ST + c8 * 8] = v;
        }
    } else {
        #pragma unroll
        for (int i = tid; i < 64 * (F_IN / 4); i += 256) {
            int r = i / (F_IN / 4), kq = i % (F_IN / 4);
            int row = row0 + r;
            float4 v = make_float4(0.f, 0.f, 0.f, 0.f);
            if (row < n) v = *(const float4*)(in32 + (size_t)row * F_IN + kq * 4);
            __half2 p0 = __floats2half2_rn(v.x, v.y);
            __half2 p1 = __floats2half2_rn(v.z, v.w);
            uint2 pk;
            pk.x = *(unsigned int*)&p0;
            pk.y = *(unsigned int*)&p1;
            *(uint2*)&As[r * ST + kq * 4] = pk;
        }
    }
    #pragma unroll 2
    for (int i = tid; i < 64 * F_IN; i += 256) {
        int nn = i & 63, k = i >> 6;
        WTs[nn * ST + k] = __float2half_rn(W[k * HID + nn]);
    }
    __syncthreads();

    float acc[4][4];
    #pragma unroll
    for (int t = 0; t < 4; t++)
        #pragma unroll
        for (int c = 0; c < 4; c++) acc[t][c] = 0.0f;

    #pragma unroll
    for (int ks = 0; ks < F_IN / 16; ks++) {
        const int abase = (wr * 16 + l4) * ST + ks * 16 + l2;
        unsigned int a0 = *(const unsigned int*)&As[abase];
        unsigned int a1 = *(const unsigned int*)&As[abase + 8 * ST];
        unsigned int a2 = *(const unsigned int*)&As[abase + 8];
        unsigned int a3 = *(const unsigned int*)&As[abase + 8 * ST + 8];
        #pragma unroll
        for (int nt = 0; nt < 4; nt++) {
            const int bbase = (wc * 32 + nt * 8 + l4) * ST + ks * 16 + l2;
            unsigned int b0 = *(const unsigned int*)&WTs[bbase];
            unsigned int b1 = *(const unsigned int*)&WTs[bbase + 8];
            asm volatile(
                "mma.sync.aligned.m16n8k16.row.col.f32.f16.f16.f32 "
                "{%0,%1,%2,%3}, {%4,%5,%6,%7}, {%8,%9}, {%0,%1,%2,%3};"
                : "+f"(acc[nt][0]), "+f"(acc[nt][1]), "+f"(acc[nt][2]), "+f"(acc[nt][3])
                : "r"(a0), "r"(a1), "r"(a2), "r"(a3), "r"(b0), "r"(b1));
        }
    }

    #pragma unroll
    for (int nt = 0; nt < 4; nt++) {
        int col = wc * 32 + nt * 8 + l2;
        int rA = row0 + wr * 16 + l4;
        int rB = rA + 8;
        __half2 pA = __floats2half2_rn(acc[nt][0], acc[nt][1]);
        __half2 pB = __floats2half2_rn(acc[nt][2], acc[nt][3]);
        if (rA < n) *(unsigned int*)&g_h[(size_t)rA * HID + col] = *(unsigned int*)&pA;
        if (rB < n) *(unsigned int*)&g_h[(size_t)rB * HID + col] = *(unsigned int*)&pB;
    }
}

// ---------------- CSR gather v2: warp per node, 2 edges per iteration -------
// lane l: half-warp sub = l>>4 covers edge p+sub, feats 4*(l&15)..+4 (uint2 of fp16).
__global__ void __launch_bounds__(256) k_gather(const float* __restrict__ b, int n) {
    const int warp = threadIdx.x >> 5;
    const int lane = threadIdx.x & 31;
    const int i = blockIdx.x * 8 + warp;       // node
    if (i >= n) return;
    const int sub = lane >> 4;                 // 0/1
    const int f   = lane & 15;                 // uint2 index: feats [4f, 4f+4)

    int beg = g_rowstart[i], end = g_rowstart[i + 1];
    const uint2* __restrict__ hp = (const uint2*)g_h;

    float a0, a1, a2, a3;
    if (sub == 0) {
        float di = g_dinv[i];
        float nm0 = di * di;
        uint2 hs = hp[i * 16 + f];
        float2 s0 = __half22float2(*(const __half2*)&hs.x);
        float2 s1 = __half22float2(*(const __half2*)&hs.y);
        float4 bb = ((const float4*)b)[f];
        a0 = fmaf(s0.x, nm0, bb.x);
        a1 = fmaf(s0.y, nm0, bb.y);
        a2 = fmaf(s1.x, nm0, bb.z);
        a3 = fmaf(s1.y, nm0, bb.w);
    } else {
        a0 = a1 = a2 = a3 = 0.0f;
    }

    #pragma unroll 2
    for (int p0 = beg; p0 < end; p0 += 2) {
        int p = p0 + sub;
        if (p < end) {
            int2 md = g_cedge[p];              // broadcast within half-warp
            float nm = __int_as_float(md.y);
            uint2 hv = hp[md.x * 16 + f];      // 16 lanes x 8B = 128B coalesced
            float2 f0 = __half22float2(*(const __half2*)&hv.x);
            float2 f1 = __half22float2(*(const __half2*)&hv.y);
            a0 = fmaf(f0.x, nm, a0);
            a1 = fmaf(f0.y, nm, a1);
            a2 = fmaf(f1.x, nm, a2);
            a3 = fmaf(f1.y, nm, a3);
        }
    }

    // combine halves
    a0 += __shfl_down_sync(0xffffffffu, a0, 16);
    a1 += __shfl_down_sync(0xffffffffu, a1, 16);
    a2 += __shfl_down_sync(0xffffffffu, a2, 16);
    a3 += __shfl_down_sync(0xffffffffu, a3, 16);

    if (sub == 0) {
        __half2 o0 = __floats2half2_rn(fmaxf(a0, 0.f), fmaxf(a1, 0.f));
        __half2 o1 = __floats2half2_rn(fmaxf(a2, 0.f), fmaxf(a3, 0.f));
        uint2 pk;
        pk.x = *(unsigned int*)&o0;
        pk.y = *(unsigned int*)&o1;
        ((uint2*)g_act)[i * 16 + f] = pk;
    }
}

// ---------------- pooling: mean over sorted batch (g_act already relu'd) ----
__global__ void k_pool(const void* __restrict__ batch, int n) {
    int idx = blockIdx.x * blockDim.x + threadIdx.x;
    int nstrips = (n + 63) / 64;
    if (idx >= nstrips * 8) return;
    int strip = idx >> 3, q = idx & 7;
    int i0 = strip * 64;
    int i1 = min(i0 + 64, n);
    float a0 = 0, a1 = 0, a2 = 0, a3 = 0, a4 = 0, a5 = 0, a6 = 0, a7 = 0;
    float cnt = 0.f;
    int gcur = fetch_idx(batch, i0);
    const uint4* ap = (const uint4*)g_act;
    for (int i = i0; i < i1; i++) {
        int g = fetch_idx(batch, i);
        if (g != gcur) {
            float* pp = &g_pool[gcur * 64 + q * 8];
            atomicAdd(pp + 0, a0); atomicAdd(pp + 1, a1);
            atomicAdd(pp + 2, a2); atomicAdd(pp + 3, a3);
            atomicAdd(pp + 4, a4); atomicAdd(pp + 5, a5);
            atomicAdd(pp + 6, a6); atomicAdd(pp + 7, a7);
            if (q == 0) atomicAdd(&g_cnt[gcur], cnt);
            a0 = a1 = a2 = a3 = a4 = a5 = a6 = a7 = 0.f; cnt = 0.f; gcur = g;
        }
        uint4 hv = ap[i * 8 + q];
        float2 f0 = __half22float2(*(const __half2*)&hv.x);
        float2 f1 = __half22float2(*(const __half2*)&hv.y);
        float2 f2 = __half22float2(*(const __half2*)&hv.z);
        float2 f3 = __half22float2(*(const __half2*)&hv.w);
        a0 += f0.x; a1 += f0.y; a2 += f1.x; a3 += f1.y;
        a4 += f2.x; a5 += f2.y; a6 += f3.x; a7 += f3.y;
        cnt += 1.0f;
    }
    float* pp = &g_pool[gcur * 64 + q * 8];
    atomicAdd(pp + 0, a0); atomicAdd(pp + 1, a1);
    atomicAdd(pp + 2, a2); atomicAdd(pp + 3, a3);
    atomicAdd(pp + 4, a4); atomicAdd(pp + 5, a5);
    atomicAdd(pp + 6, a6); atomicAdd(pp + 7, a7);
    if (q == 0) atomicAdd(&g_cnt[gcur], cnt);
}

// ---------------- final: linear + softmax ----------------
__global__ void k_final(const float* __restrict__ Wl, const float* __restrict__ bl,
                        float* __restrict__ out) {
    int g = threadIdx.x;
    if (g >= NG) return;
    float inv = 1.0f / fmaxf(g_cnt[g], 1.0f);
    float logits[NC];
    #pragma unroll
    for (int c = 0; c < NC; c++) logits[c] = bl[c];
    for (int f = 0; f < HID; f++) {
        float p = g_pool[g * HID + f] * inv;
        #pragma unroll
        for (int c = 0; c < NC; c++) logits[c] = fmaf(p, Wl[f * NC + c], logits[c]);
    }
    float mx = logits[0];
    #pragma unroll
    for (int c = 1; c < NC; c++) mx = fmaxf(mx, logits[c]);
    float s = 0.0f;
    #pragma unroll
    for (int c = 0; c < NC; c++) { logits[c] = expf(logits[c] - mx); s += logits[c]; }
    float is = 1.0f / s;
    #pragma unroll
    for (int c = 0; c < NC; c++) out[g * NC + c] = logits[c] * is;
}

extern "C" void kernel_launch(void* const* d_in, const int* in_sizes, int n_in,
                              void* d_out, int out_size) {
    const float* x     = (const float*)d_in[0];
    const void*  ei    = d_in[1];
    const void*  batch = d_in[2];
    const float* W1 = (const float*)d_in[3];
    const float* b1 = (const float*)d_in[4];
    const float* W2 = (const float*)d_in[5];
    const float* b2 = (const float*)d_in[6];
    const float* W3 = (const float*)d_in[7];
    const float* b3 = (const float*)d_in[8];
    const float* Wl = (const float*)d_in[9];
    const float* bl = (const float*)d_in[10];

    const int n = in_sizes[0] / F0;
    const int E = in_sizes[1] / 2;

    const int TB = 256;
    const int nb_scan = (n + SCAN_B - 1) / SCAN_B;

    // init + degree + CSR build
    k_init<<<(n + TB - 1) / TB, TB>>>((const int*)ei, n);
    k_deg<<<(E + TB - 1) / TB, TB>>>(ei, E);
    k_scan1<<<nb_scan, SCAN_B>>>(n);
    k_scan2<<<1, MAX_PART>>>(nb_scan);
    k_scan3<<<(n + TB - 1) / TB, TB>>>(n, E);
    k_fill<<<(E + TB - 1) / TB, TB>>>(ei, E);

    const int gGemm = (n + 63) / 64;
    const int gWpn  = (n + 7) / 8;

    // layer 1
    k_gemm<F0, false><<<gGemm, TB>>>(x, W1, n);
    k_gather<<<gWpn, TB>>>(b1, n);
    // layer 2
    k_gemm<HID, true><<<gGemm, TB>>>(x, W2, n);
    k_gather<<<gWpn, TB>>>(b2, n);
    // layer 3
    k_gemm<HID, true><<<gGemm, TB>>>(x, W3, n);
    k_gather<<<gWpn, TB>>>(b3, n);

    // pooling + head
    int nstrips = (n + 63) / 64;
    k_pool<<<(nstrips * 8 + TB - 1) / TB, TB>>>(batch, n);
    k_final<<<1, NG>>>(Wl, bl, (float*)d_out);
}

// round 12
// speedup vs baseline: 1.1256x; 1.1256x over previous
#include <cuda_runtime.h>
#include <cuda_fp16.h>
#include <math.h>

#define F0   128
#define HID  64
#define NG   64
#define NC   10
#define MAXN 100000
#define MAXE 1600000
#define SCAN_B 512
#define MAX_PART 256

// ---- scratch (no allocs allowed) ----
__device__ int    g_is64;
__device__ int    g_idc [MAXN];
__device__ float  g_dinv[MAXN];
__device__ int    g_rowstart[MAXN + 1];
__device__ int    g_cursor[MAXN];
__device__ int    g_part[MAX_PART];
__device__ int2   g_cedge[MAXE];         // CSR slot: (src, float_as_int(norm))
__device__ __half g_h   [MAXN * HID];    // h = act @ W   (fp16, pre-relu)
__device__ __half g_act [MAXN * HID];    // relu(agg)     (fp16)
__device__ float  g_pool[NG * HID];
__device__ float  g_cnt [NG];

__device__ __forceinline__ int fetch_idx(const void* p, long long i) {
    if (g_is64) return (int)((const long long*)p)[i];
    return ((const int*)p)[i];
}

// ---------------- fused init: dtype detect + zero idc + zero pool ----------
__global__ void k_init(const int* __restrict__ ei, int n) {
    int i = blockIdx.x * blockDim.x + threadIdx.x;
    if (i < n) g_idc[i] = 0;
    if (i < NG * HID) g_pool[i] = 0.0f;
    if (i < NG) g_cnt[i] = 0.0f;
    if (blockIdx.x == 0) {
        __shared__ int s[256];
        int acc = 0;
        for (int j = threadIdx.x; j < 1024; j += 256) acc |= ei[2 * j + 1];
        s[threadIdx.x] = acc;
        __syncthreads();
        for (int d = 128; d; d >>= 1) {
            if (threadIdx.x < d) s[threadIdx.x] |= s[threadIdx.x + d];
            __syncthreads();
        }
        if (threadIdx.x == 0) g_is64 = (s[0] == 0) ? 1 : 0;
    }
}

__global__ void k_deg(const void* __restrict__ ei, int e) {
    int i = blockIdx.x * blockDim.x + threadIdx.x;
    if (i < e) atomicAdd(&g_idc[fetch_idx(ei, (long long)e + i)], 1);
}

// ---------------- scan (+ dinv fused) ----------------
__global__ void k_scan1(int n) {
    __shared__ int s[SCAN_B];
    int i = blockIdx.x * SCAN_B + threadIdx.x;
    int v = (i < n) ? g_idc[i] : 0;
    if (i < n) g_dinv[i] = rsqrtf((float)(v + 1));
    s[threadIdx.x] = v;
    __syncthreads();
    int incl = v;
    #pragma unroll
    for (int d = 1; d < SCAN_B; d <<= 1) {
        int t = (threadIdx.x >= d) ? s[threadIdx.x - d] : 0;
        __syncthreads();
        incl += t;
        s[threadIdx.x] = incl;
        __syncthreads();
    }
    if (i < n) g_rowstart[i] = incl - v;
    if (threadIdx.x == SCAN_B - 1) g_part[blockIdx.x] = incl;
}
__global__ void k_scan2(int nb) {
    __shared__ int s[MAX_PART];
    int v = (threadIdx.x < nb) ? g_part[threadIdx.x] : 0;
    s[threadIdx.x] = v;
    __syncthreads();
    int incl = v;
    #pragma unroll
    for (int d = 1; d < MAX_PART; d <<= 1) {
        int t = (threadIdx.x >= d) ? s[threadIdx.x - d] : 0;
        __syncthreads();
        incl += t;
        s[threadIdx.x] = incl;
        __syncthreads();
    }
    if (threadIdx.x < nb) g_part[threadIdx.x] = incl - v;
}
__global__ void k_scan3(int n, int e) {
    int i = blockIdx.x * blockDim.x + threadIdx.x;
    if (i < n) {
        int r = g_rowstart[i] + g_part[i / SCAN_B];
        g_rowstart[i] = r;
        g_cursor[i] = r;
    }
    if (i == 0) g_rowstart[n] = e;
}

__global__ void k_fill(const void* __restrict__ ei, int e) {
    int i = blockIdx.x * blockDim.x + threadIdx.x;
    if (i < e) {
        int s = fetch_idx(ei, i);
        int d = fetch_idx(ei, (long long)e + i);
        int pos = atomicAdd(&g_cursor[d], 1);
        g_cedge[pos] = make_int2(s, __float_as_int(g_dinv[s] * g_dinv[d]));
    }
}

// ---------------- GEMM (tensor cores): g_h(fp16) = A @ W ---------------------
template<int F_IN, bool FP16IN>
__global__ void __launch_bounds__(256) k_gemm(const float* __restrict__ in32,
                                              const float* __restrict__ W, int n) {
    constexpr int ST = F_IN + 8;               // smem stride in halves
    __shared__ __half As [64 * ST];
    __shared__ __half WTs[64 * ST];            // W^T: [n][k]
    const int tid   = threadIdx.x;
    const int row0  = blockIdx.x * 64;
    const int lane  = tid & 31;
    const int warp  = tid >> 5;
    const int wr    = warp >> 1;               // row group 0..3
    const int wc    = warp & 1;                // col group 0..1
    const int l4    = lane >> 2;
    const int l2    = (lane & 3) * 2;

    if (FP16IN) {
        #pragma unroll
        for (int i = tid; i < 64 * (F_IN / 8); i += 256) {
            int r = i / (F_IN / 8), c8 = i % (F_IN / 8);
            int row = row0 + r;
            uint4 v = make_uint4(0u, 0u, 0u, 0u);
            if (row < n) v = *(const uint4*)&g_act[(size_t)row * HID + c8 * 8];
            *(uint4*)&As[r * ST + c8 * 8] = v;
        }
    } else {
        #pragma unroll
        for (int i = tid; i < 64 * (F_IN / 4); i += 256) {
            int r = i / (F_IN / 4), kq = i % (F_IN / 4);
            int row = row0 + r;
            float4 v = make_float4(0.f, 0.f, 0.f, 0.f);
            if (row < n) v = *(const float4*)(in32 + (size_t)row * F_IN + kq * 4);
            __half2 p0 = __floats2half2_rn(v.x, v.y);
            __half2 p1 = __floats2half2_rn(v.z, v.w);
            uint2 pk;
            pk.x = *(unsigned int*)&p0;
            pk.y = *(unsigned int*)&p1;
            *(uint2*)&As[r * ST + kq * 4] = pk;
        }
    }
    #pragma unroll 2
    for (int i = tid; i < 64 * F_IN; i += 256) {
        int nn = i & 63, k = i >> 6;
        WTs[nn * ST + k] = __float2half_rn(W[k * HID + nn]);
    }
    __syncthreads();

    float acc[4][4];
    #pragma unroll
    for (int t = 0; t < 4; t++)
        #pragma unroll
        for (int c = 0; c < 4; c++) acc[t][c] = 0.0f;

    #pragma unroll
    for (int ks = 0; ks < F_IN / 16; ks++) {
        const int abase = (wr * 16 + l4) * ST + ks * 16 + l2;
        unsigned int a0 = *(const unsigned int*)&As[abase];
        unsigned int a1 = *(const unsigned int*)&As[abase + 8 * ST];
        unsigned int a2 = *(const unsigned int*)&As[abase + 8];
        unsigned int a3 = *(const unsigned int*)&As[abase + 8 * ST + 8];
        #pragma unroll
        for (int nt = 0; nt < 4; nt++) {
            const int bbase = (wc * 32 + nt * 8 + l4) * ST + ks * 16 + l2;
            unsigned int b0 = *(const unsigned int*)&WTs[bbase];
            unsigned int b1 = *(const unsigned int*)&WTs[bbase + 8];
            asm volatile(
                "mma.sync.aligned.m16n8k16.row.col.f32.f16.f16.f32 "
                "{%0,%1,%2,%3}, {%4,%5,%6,%7}, {%8,%9}, {%0,%1,%2,%3};"
                : "+f"(acc[nt][0]), "+f"(acc[nt][1]), "+f"(acc[nt][2]), "+f"(acc[nt][3])
                : "r"(a0), "r"(a1), "r"(a2), "r"(a3), "r"(b0), "r"(b1));
        }
    }

    #pragma unroll
    for (int nt = 0; nt < 4; nt++) {
        int col = wc * 32 + nt * 8 + l2;
        int rA = row0 + wr * 16 + l4;
        int rB = rA + 8;
        __half2 pA = __floats2half2_rn(acc[nt][0], acc[nt][1]);
        __half2 pB = __floats2half2_rn(acc[nt][2], acc[nt][3]);
        if (rA < n) *(unsigned int*)&g_h[(size_t)rA * HID + col] = *(unsigned int*)&pA;
        if (rB < n) *(unsigned int*)&g_h[(size_t)rB * HID + col] = *(unsigned int*)&pB;
    }
}

// ---------------- CSR gather (R10 shape + 2-deep software pipeline) ---------
// 8 threads per node; each handles 8 feats (one LDG.128 of 8 halves per edge).
__global__ void __launch_bounds__(256) k_gather(const float* __restrict__ b, int n) {
    int idx = blockIdx.x * blockDim.x + threadIdx.x;   // n*8 threads
    if (idx >= n * 8) return;
    int i = idx >> 3, q = idx & 7;
    int p = g_rowstart[i], end = g_rowstart[i + 1];
    float di = g_dinv[i];
    float nm0 = di * di;

    const uint4* __restrict__ hp = (const uint4*)g_h;   // 16B = 8 halves
    uint4 hs = hp[i * 8 + q];
    float2 s0 = __half22float2(*(const __half2*)&hs.x);
    float2 s1 = __half22float2(*(const __half2*)&hs.y);
    float2 s2 = __half22float2(*(const __half2*)&hs.z);
    float2 s3 = __half22float2(*(const __half2*)&hs.w);
    float4 b0 = ((const float4*)b)[q * 2 + 0];
    float4 b1 = ((const float4*)b)[q * 2 + 1];

    float a0 = fmaf(s0.x, nm0, b0.x), a1 = fmaf(s0.y, nm0, b0.y);
    float a2 = fmaf(s1.x, nm0, b0.z), a3 = fmaf(s1.y, nm0, b0.w);
    float a4 = fmaf(s2.x, nm0, b1.x), a5 = fmaf(s2.y, nm0, b1.y);
    float a6 = fmaf(s3.x, nm0, b1.z), a7 = fmaf(s3.y, nm0, b1.w);

    if (p < end) {
        // prologue: issue loads for first edge
        int2 md = g_cedge[p];
        uint4 hv = hp[md.x * 8 + q];
        #pragma unroll 2
        while (++p < end) {
            // issue next edge's loads before consuming current
            int2 mdn = g_cedge[p];
            uint4 hvn = hp[mdn.x * 8 + q];
            float nm = __int_as_float(md.y);
            float2 f0 = __half22float2(*(const __half2*)&hv.x);
            float2 f1 = __half22float2(*(const __half2*)&hv.y);
            float2 f2 = __half22float2(*(const __half2*)&hv.z);
            float2 f3 = __half22float2(*(const __half2*)&hv.w);
            a0 = fmaf(f0.x, nm, a0); a1 = fmaf(f0.y, nm, a1);
            a2 = fmaf(f1.x, nm, a2); a3 = fmaf(f1.y, nm, a3);
            a4 = fmaf(f2.x, nm, a4); a5 = fmaf(f2.y, nm, a5);
            a6 = fmaf(f3.x, nm, a6); a7 = fmaf(f3.y, nm, a7);
            md = mdn; hv = hvn;
        }
        // epilogue
        float nm = __int_as_float(md.y);
        float2 f0 = __half22float2(*(const __half2*)&hv.x);
        float2 f1 = __half22float2(*(const __half2*)&hv.y);
        float2 f2 = __half22float2(*(const __half2*)&hv.z);
        float2 f3 = __half22float2(*(const __half2*)&hv.w);
        a0 = fmaf(f0.x, nm, a0); a1 = fmaf(f0.y, nm, a1);
        a2 = fmaf(f1.x, nm, a2); a3 = fmaf(f1.y, nm, a3);
        a4 = fmaf(f2.x, nm, a4); a5 = fmaf(f2.y, nm, a5);
        a6 = fmaf(f3.x, nm, a6); a7 = fmaf(f3.y, nm, a7);
    }

    // relu + fp16 pack
    __half2 o0 = __floats2half2_rn(fmaxf(a0, 0.f), fmaxf(a1, 0.f));
    __half2 o1 = __floats2half2_rn(fmaxf(a2, 0.f), fmaxf(a3, 0.f));
    __half2 o2 = __floats2half2_rn(fmaxf(a4, 0.f), fmaxf(a5, 0.f));
    __half2 o3 = __floats2half2_rn(fmaxf(a6, 0.f), fmaxf(a7, 0.f));
    uint4 pk;
    pk.x = *(unsigned int*)&o0; pk.y = *(unsigned int*)&o1;
    pk.z = *(unsigned int*)&o2; pk.w = *(unsigned int*)&o3;
    ((uint4*)g_act)[idx] = pk;
}

// ---------------- pooling: mean over sorted batch (g_act already relu'd) ----
__global__ void k_pool(const void* __restrict__ batch, int n) {
    int idx = blockIdx.x * blockDim.x + threadIdx.x;
    int nstrips = (n + 63) / 64;
    if (idx >= nstrips * 8) return;
    int strip = idx >> 3, q = idx & 7;
    int i0 = strip * 64;
    int i1 = min(i0 + 64, n);
    float a0 = 0, a1 = 0, a2 = 0, a3 = 0, a4 = 0, a5 = 0, a6 = 0, a7 = 0;
    float cnt = 0.f;
    int gcur = fetch_idx(batch, i0);
    const uint4* ap = (const uint4*)g_act;
    for (int i = i0; i < i1; i++) {
        int g = fetch_idx(batch, i);
        if (g != gcur) {
            float* pp = &g_pool[gcur * 64 + q * 8];
            atomicAdd(pp + 0, a0); atomicAdd(pp + 1, a1);
            atomicAdd(pp + 2, a2); atomicAdd(pp + 3, a3);
            atomicAdd(pp + 4, a4); atomicAdd(pp + 5, a5);
            atomicAdd(pp + 6, a6); atomicAdd(pp + 7, a7);
            if (q == 0) atomicAdd(&g_cnt[gcur], cnt);
            a0 = a1 = a2 = a3 = a4 = a5 = a6 = a7 = 0.f; cnt = 0.f; gcur = g;
        }
        uint4 hv = ap[i * 8 + q];
        float2 f0 = __half22float2(*(const __half2*)&hv.x);
        float2 f1 = __half22float2(*(const __half2*)&hv.y);
        float2 f2 = __half22float2(*(const __half2*)&hv.z);
        float2 f3 = __half22float2(*(const __half2*)&hv.w);
        a0 += f0.x; a1 += f0.y; a2 += f1.x; a3 += f1.y;
        a4 += f2.x; a5 += f2.y; a6 += f3.x; a7 += f3.y;
        cnt += 1.0f;
    }
    float* pp = &g_pool[gcur * 64 + q * 8];
    atomicAdd(pp + 0, a0); atomicAdd(pp + 1, a1);
    atomicAdd(pp + 2, a2); atomicAdd(pp + 3, a3);
    atomicAdd(pp + 4, a4); atomicAdd(pp + 5, a5);
    atomicAdd(pp + 6, a6); atomicAdd(pp + 7, a7);
    if (q == 0) atomicAdd(&g_cnt[gcur], cnt);
}

// ---------------- final: linear + softmax ----------------
__global__ void k_final(const float* __restrict__ Wl, const float* __restrict__ bl,
                        float* __restrict__ out) {
    int g = threadIdx.x;
    if (g >= NG) return;
    float inv = 1.0f / fmaxf(g_cnt[g], 1.0f);
    float logits[NC];
    #pragma unroll
    for (int c = 0; c < NC; c++) logits[c] = bl[c];
    for (int f = 0; f < HID; f++) {
        float p = g_pool[g * HID + f] * inv;
        #pragma unroll
        for (int c = 0; c < NC; c++) logits[c] = fmaf(p, Wl[f * NC + c], logits[c]);
    }
    float mx = logits[0];
    #pragma unroll
    for (int c = 1; c < NC; c++) mx = fmaxf(mx, logits[c]);
    float s = 0.0f;
    #pragma unroll
    for (int c = 0; c < NC; c++) { logits[c] = expf(logits[c] - mx); s += logits[c]; }
    float is = 1.0f / s;
    #pragma unroll
    for (int c = 0; c < NC; c++) out[g * NC + c] = logits[c] * is;
}

extern "C" void kernel_launch(void* const* d_in, const int* in_sizes, int n_in,
                              void* d_out, int out_size) {
    const float* x     = (const float*)d_in[0];
    const void*  ei    = d_in[1];
    const void*  batch = d_in[2];
    const float* W1 = (const float*)d_in[3];
    const float* b1 = (const float*)d_in[4];
    const float* W2 = (const float*)d_in[5];
    const float* b2 = (const float*)d_in[6];
    const float* W3 = (const float*)d_in[7];
    const float* b3 = (const float*)d_in[8];
    const float* Wl = (const float*)d_in[9];
    const float* bl = (const float*)d_in[10];

    const int n = in_sizes[0] / F0;
    const int E = in_sizes[1] / 2;

    const int TB = 256;
    const int nb_scan = (n + SCAN_B - 1) / SCAN_B;

    // init + degree + CSR build
    k_init<<<(n + TB - 1) / TB, TB>>>((const int*)ei, n);
    k_deg<<<(E + TB - 1) / TB, TB>>>(ei, E);
    k_scan1<<<nb_scan, SCAN_B>>>(n);
    k_scan2<<<1, MAX_PART>>>(nb_scan);
    k_scan3<<<(n + TB - 1) / TB, TB>>>(n, E);
    k_fill<<<(E + TB - 1) / TB, TB>>>(ei, E);

    const int gGemm = (n + 63) / 64;
    const int gN8   = (n * 8 + TB - 1) / TB;

    // layer 1
    k_gemm<F0, false><<<gGemm, TB>>>(x, W1, n);
    k_gather<<<gN8, TB>>>(b1, n);
    // layer 2
    k_gemm<HID, true><<<gGemm, TB>>>(x, W2, n);
    k_gather<<<gN8, TB>>>(b2, n);
    // layer 3
    k_gemm<HID, true><<<gGemm, TB>>>(x, W3, n);
    k_gather<<<gN8, TB>>>(b3, n);

    // pooling + head
    int nstrips = (n + 63) / 64;
    k_pool<<<(nstrips * 8 + TB - 1) / TB, TB>>>(batch, n);
    k_final<<<1, NG>>>(Wl, bl, (float*)d_out);
}